// round 16
// baseline (speedup 1.0000x reference)
#include <cuda_runtime.h>
#include <stdint.h>

typedef uint32_t u32;

#define T_LEN 1024
#define NTH   256
#define QP 136              // Q/K tile pitch (floats)
#define VP 132              // V tile pitch
#define PP 68               // P scratch pitch (s64 + pad)

// ---- smem byte layout ----
#define OFF_MASK 0          // 4096B: full mask row (static; reused as sums in epi)
#define OFF_P    4096       // 8 warps x 32 x 68 f32 = 69632B; Q tile overlays base
#define OFF_K0   73728      // 64 x 136 f32 = 34816B
#define OFF_K1   108544
#define OFF_V0   143360     // 64 x 132 f32 = 33792B
#define OFF_V1   177152
#define SMEM_BYTES 210944

__device__ __forceinline__ u32 smem_u32(const void* p) {
    u32 a;
    asm("{ .reg .u64 t; cvta.to.shared.u64 t, %1; cvt.u32.u64 %0, t; }"
        : "=r"(a) : "l"(p));
    return a;
}
__device__ __forceinline__ float rtf(float x) {       // round to tf32
    float r;
    asm("cvt.rna.tf32.f32 %0, %1;" : "=f"(r) : "f"(x));
    return r;
}
__device__ __forceinline__ void mma_tf32(float* d, const float* a, float b0, float b1) {
    asm volatile("mma.sync.aligned.m16n8k8.row.col.f32.tf32.tf32.f32 "
        "{%0,%1,%2,%3}, {%4,%5,%6,%7}, {%8,%9}, {%0,%1,%2,%3};"
        : "+f"(d[0]), "+f"(d[1]), "+f"(d[2]), "+f"(d[3])
        : "r"(__float_as_uint(a[0])), "r"(__float_as_uint(a[1])),
          "r"(__float_as_uint(a[2])), "r"(__float_as_uint(a[3])),
          "r"(__float_as_uint(b0)), "r"(__float_as_uint(b1)));
}
#define CP16(dst, src) \
    asm volatile("cp.async.cg.shared.global [%0], [%1], 16;" \
                 :: "r"(dst), "l"(__cvta_generic_to_global(src)) : "memory")
#define CP_COMMIT() asm volatile("cp.async.commit_group;" ::: "memory")
#define CP_WAIT0()  asm volatile("cp.async.wait_group 0;" ::: "memory")

__device__ __forceinline__ void cp_tile(u32 dst, const float* __restrict__ g,
                                        int col0, int pitchB, int tid) {
    #pragma unroll
    for (int f = tid; f < 2048; f += NTH) {
        int c = f >> 5, j = f & 31;
        CP16(dst + (u32)c * pitchB + (u32)j * 16, g + (size_t)c * T_LEN + col0 + 4 * j);
    }
}
__device__ __forceinline__ void round_tile(char* sm, u32 off, int pitchB,
                                           float sc, int tid) {
    #pragma unroll
    for (int f = tid; f < 2048; f += NTH) {
        int c = f >> 5, j = f & 31;
        float4* p = (float4*)(sm + off + (u32)c * pitchB + (u32)j * 16);
        float4 v = *p;
        v.x = rtf(v.x * sc); v.y = rtf(v.y * sc);
        v.z = rtf(v.z * sc); v.w = rtf(v.w * sc);
        *p = v;
    }
}

// S-chunk (s16 block gp of this warp's s-half) + softmax + P-slot store
__device__ __forceinline__ void s_sm_chunk(
    int gp, const float* __restrict__ kbuf, const float* __restrict__ mrow,
    const float (&aQ)[8][2][4], float* __restrict__ Pw,
    float (&lsum)[2][2], int h, int gid, int tig)
{
    float ac[2][2][4];
    #pragma unroll
    for (int e = 0; e < 2; e++)
        #pragma unroll
        for (int tt = 0; tt < 2; tt++)
            #pragma unroll
            for (int r = 0; r < 4; r++) ac[e][tt][r] = 0.0f;
    const int s0a = h * 64 + gp * 16 + gid;
    #pragma unroll
    for (int k = 0; k < 8; k++) {
        const float* kb = kbuf + (k * 8 + tig) * QP;
        float b00 = kb[s0a],      b01 = kb[4 * QP + s0a];
        float b10 = kb[s0a + 8],  b11 = kb[4 * QP + s0a + 8];
        #pragma unroll
        for (int tt = 0; tt < 2; tt++) {
            mma_tf32(ac[0][tt], aQ[k][tt], b00, b01);
            mma_tf32(ac[1][tt], aQ[k][tt], b10, b11);
        }
    }
    #pragma unroll
    for (int e = 0; e < 2; e++) {
        float2 mm = *(const float2*)(mrow + gp * 16 + e * 8 + 2 * tig);
        #pragma unroll
        for (int tt = 0; tt < 2; tt++) {
            float* a = ac[e][tt];
            float e0 = __expf(a[0] * mm.x), e1 = __expf(a[1] * mm.y);
            float e2 = __expf(a[2] * mm.x), e3 = __expf(a[3] * mm.y);
            lsum[tt][0] += e0 + e1; lsum[tt][1] += e2 + e3;
            float* pr = Pw + (tt * 16 + gid) * PP + gp * 16 + e * 8 + 2 * tig;
            *(float2*)pr = make_float2(rtf(e0), rtf(e1));
            *(float2*)(pr + 8 * PP) = make_float2(rtf(e2), rtf(e3));
        }
    }
}

// PV-chunk: consume P slot gp (ks = 2gp, 2gp+1) against V s-half h
__device__ __forceinline__ void pv_chunk(
    int gp, const float* __restrict__ vbuf, const float* __restrict__ Pw,
    float (&oacc)[4][4][4], int h, int gid, int tig)
{
    #pragma unroll
    for (int kk = 0; kk < 2; kk++) {
        const int ks = 2 * gp + kk;
        float av[4][4];
        #pragma unroll
        for (int cm = 0; cm < 4; cm++) {
            const float* vb = vbuf + (cm * 16 + gid) * VP + h * 64 + ks * 8 + tig;
            av[cm][0] = vb[0];
            av[cm][1] = vb[8 * VP];
            av[cm][2] = vb[4];
            av[cm][3] = vb[8 * VP + 4];
        }
        #pragma unroll
        for (int nt = 0; nt < 4; nt++) {
            const float* pb = Pw + (nt * 8 + gid) * PP + ks * 8 + tig;
            float b0 = pb[0], b1 = pb[4];
            #pragma unroll
            for (int cm = 0; cm < 4; cm++)
                mma_tf32(oacc[cm][nt], av[cm], b0, b1);
        }
    }
}

__global__ __launch_bounds__(NTH, 1)
void qkv_attn_tf32(const float* __restrict__ qkv,
                   const float* __restrict__ mask,
                   float* __restrict__ out)
{
    extern __shared__ char sm[];
    const u32 sb = smem_u32(sm);                 // used ONLY for cp.async dst
    const int tid = threadIdx.x, wid = tid >> 5, lane = tid & 31;
    const int gid = lane >> 2, tig = lane & 3;
    const int wq = wid & 3;                      // t-block index (32 t each)
    const int h  = wid >> 2;                     // s-half owned by this warp
    const int t0 = blockIdx.x * 128;
    const u32 bh = blockIdx.y;                   // b*16 + h
    const float* qg = qkv + (size_t)((bh >> 4) * 3072 + (bh & 15) * 64) * T_LEN;
    const float* kg = qg + (size_t)1024 * T_LEN;
    const float* vg = qg + (size_t)2048 * T_LEN;
    const float* mg = mask + (size_t)(bh & 7) * T_LEN;   // torch repeat: row = bh % 8

    const int tw = wq * 32;
    float* Pw = (float*)(sm + OFF_P) + wid * (32 * PP);  // warp-private scratch
    const float* mbase = (const float*)(sm + OFF_MASK);

    // ---- prologue: Q (into P overlay) + K0/V0 + full mask row ----
    cp_tile(sb + OFF_P, qg, t0, QP * 4, tid);
    cp_tile(sb + OFF_K0, kg, 0, QP * 4, tid);
    cp_tile(sb + OFF_V0, vg, 0, VP * 4, tid);
    CP16(sb + OFF_MASK + tid * 16, mg + tid * 4);        // 256 x 16B = 4KB
    CP_COMMIT();
    CP_WAIT0();
    round_tile(sm, OFF_P,  QP * 4, 0.125f, tid);         // attn scale^2 into Q
    round_tile(sm, OFF_K0, QP * 4, 1.0f, tid);
    round_tile(sm, OFF_V0, VP * 4, 1.0f, tid);
    __syncthreads();

    float aQ[8][2][4];                           // persistent Q frags
    #pragma unroll
    for (int k = 0; k < 8; k++)
        #pragma unroll
        for (int tt = 0; tt < 2; tt++) {
            const float* base = (const float*)(sm + OFF_P)
                              + (k * 8 + tig) * QP + tw + tt * 16 + gid;
            aQ[k][tt][0] = base[0];
            aQ[k][tt][1] = base[8];
            aQ[k][tt][2] = base[4 * QP];
            aQ[k][tt][3] = base[4 * QP + 8];
        }
    __syncthreads();                             // Q region becomes P scratch

    cp_tile(sb + OFF_K1, kg, 128, QP * 4, tid);  // K(1) prefetch
    CP_COMMIT();

    float oacc[4][4][4];
    #pragma unroll
    for (int i = 0; i < 4; i++)
        #pragma unroll
        for (int j = 0; j < 4; j++)
            #pragma unroll
            for (int r = 0; r < 4; r++) oacc[i][j][r] = 0.0f;
    float lsum[2][2] = {{0, 0}, {0, 0}};

    // S(0) + softmax(0) -> P slots (not interleaved; one-time)
    {
        const float* mrow = mbase + h * 64;
        #pragma unroll
        for (int gp = 0; gp < 4; gp++)
            s_sm_chunk(gp, (const float*)(sm + OFF_K0), mrow, aQ, Pw, lsum,
                       h, gid, tig);
    }

    // ---- main loop: per iter, PV(it) interleaved with S(it+1)+softmax(it+1) ----
    for (int it = 0; it < 8; it++) {
        const int p = it & 1;
        CP_WAIT0();                              // K(it+1), V(it) arrived
        if (it < 7) round_tile(sm, p ? OFF_K0 : OFF_K1, QP * 4, 1.0f, tid); // K(it+1)
        if (it >= 1) round_tile(sm, p ? OFF_V1 : OFF_V0, VP * 4, 1.0f, tid); // V(it)
        __syncthreads();                         // rounded + all prior reads done

        if (it < 6) cp_tile(sb + (p ? OFF_K1 : OFF_K0), kg, (it + 2) * 128,
                            QP * 4, tid);        // K(it+2) -> buf p
        if (it < 7) cp_tile(sb + (p ? OFF_V0 : OFF_V1), vg, (it + 1) * 128,
                            VP * 4, tid);        // V(it+1) -> buf 1-p
        if (it < 7) CP_COMMIT();

        const float* vb = (const float*)(sm + (p ? OFF_V1 : OFF_V0)); // V(it)
        const float* kb = (const float*)(sm + (p ? OFF_K0 : OFF_K1)); // K(it+1)
        const float* mrow = mbase + (it + 1) * 128 + h * 64;

        #pragma unroll
        for (int gp = 0; gp < 4; gp++) {
            pv_chunk(gp, vb, Pw, oacc, h, gid, tig);   // consumes old P slot gp
            if (it < 7)
                s_sm_chunk(gp, kb, mrow, aQ, Pw, lsum, h, gid, tig); // rewrites gp
        }
    }

    // ---- epilogue: combine warp-pair partials, normalize, write ----
    #pragma unroll
    for (int tt = 0; tt < 2; tt++)
        #pragma unroll
        for (int e = 0; e < 2; e++) {
            lsum[tt][e] += __shfl_xor_sync(0xffffffffu, lsum[tt][e], 1);
            lsum[tt][e] += __shfl_xor_sync(0xffffffffu, lsum[tt][e], 2);
        }
    float* sums = (float*)(sm + OFF_MASK);       // [8 warps][32 t] (mask dead)
    if (tig == 0) {
        #pragma unroll
        for (int tt = 0; tt < 2; tt++) {
            sums[wid * 32 + tt * 16 + gid]     = lsum[tt][0];
            sums[wid * 32 + tt * 16 + 8 + gid] = lsum[tt][1];
        }
    }
    __syncthreads();                             // all P scratch dead

    float* R = (float*)(sm + OFF_P) + wq * (64 * 34);   // pair staging [64 c][34]
    if (h == 1) {                                // upper-half warp dumps partials
        #pragma unroll
        for (int cm = 0; cm < 4; cm++)
            #pragma unroll
            for (int nt = 0; nt < 4; nt++) {
                float* r0 = R + (cm * 16 + gid) * 34 + nt * 8 + 2 * tig;
                *(float2*)r0 = make_float2(oacc[cm][nt][0], oacc[cm][nt][1]);
                *(float2*)(r0 + 8 * 34) = make_float2(oacc[cm][nt][2], oacc[cm][nt][3]);
            }
    }
    __syncthreads();
    if (h == 0) {                                // lower-half warp combines + writes
        const float* sa = sums + wid * 32;
        const float* sp = sums + (wid + 4) * 32;
        float inva[4], invb[4];
        #pragma unroll
        for (int nt = 0; nt < 4; nt++) {
            int c = nt * 8 + 2 * tig;
            inva[nt] = 1.0f / (sa[c] + sp[c]);
            invb[nt] = 1.0f / (sa[c + 1] + sp[c + 1]);
        }
        float* ob = out + (size_t)bh * 64 * T_LEN + t0 + tw;
        #pragma unroll
        for (int cm = 0; cm < 4; cm++)
            #pragma unroll
            for (int nt = 0; nt < 4; nt++) {
                float* r0 = R + (cm * 16 + gid) * 34 + nt * 8 + 2 * tig;
                float2 q0 = *(float2*)r0;
                float2 q1 = *(float2*)(r0 + 8 * 34);
                float* o0 = ob + (size_t)(cm * 16 + gid) * T_LEN + nt * 8 + 2 * tig;
                *(float2*)o0 = make_float2((oacc[cm][nt][0] + q0.x) * inva[nt],
                                           (oacc[cm][nt][1] + q0.y) * invb[nt]);
                float* o1 = o0 + (size_t)8 * T_LEN;
                *(float2*)o1 = make_float2((oacc[cm][nt][2] + q1.x) * inva[nt],
                                           (oacc[cm][nt][3] + q1.y) * invb[nt]);
            }
    }
}

extern "C" void kernel_launch(void* const* d_in, const int* in_sizes, int n_in,
                              void* d_out, int out_size)
{
    const float* qkv  = (const float*)d_in[0];
    const float* mask = (const float*)d_in[1];
    float* out        = (float*)d_out;
    (void)in_sizes; (void)n_in; (void)out_size;

    cudaFuncSetAttribute(qkv_attn_tf32,
                         cudaFuncAttributeMaxDynamicSharedMemorySize, SMEM_BYTES);
    dim3 grid(T_LEN / 128, 8 * 16);
    qkv_attn_tf32<<<grid, NTH, SMEM_BYTES>>>(qkv, mask, out);
}